// round 14
// baseline (speedup 1.0000x reference)
#include <cuda_runtime.h>
#include <math.h>

typedef unsigned long long ull;

#define G    8
#define NT   1024
#define XSTR 388
#define PSTR 388

#define RT_OFF   0
#define QS_OFF   2048
#define PY_OFF   4096
#define XS_OFF   (PY_OFF + 24832)
#define XS1_OFF  (XS_OFF + 12416)
#define WO_OFF   (XS_OFF + 8192)
#define WT_OFF   (XS_OFF + 24832)
#define RD1_OFF  (WT_OFF + 256)
#define RD2_OFF  (RD1_OFF + 64)
#define MU_OFF   (RD2_OFF + 64)
#define RS_OFF   (MU_OFF + 8)
#define CODE_OFF (RS_OFF + 8)
#define LST_OFF  (CODE_OFF + 256)
#define MS_OFF   (LST_OFF + 256)
#define MB_OFF   (MS_OFF + 8)
#define SMEM_FLOATS (MB_OFF + 8)
#define SMEM_BYTES  (SMEM_FLOATS * 4)

__device__ __forceinline__ float wsum(float v) {
#pragma unroll
    for (int o = 16; o > 0; o >>= 1) v += __shfl_xor_sync(0xffffffffu, v, o);
    return v;
}
__device__ __forceinline__ float wmax(float v) {
#pragma unroll
    for (int o = 16; o > 0; o >>= 1) v = fmaxf(v, __shfl_xor_sync(0xffffffffu, v, o));
    return v;
}
__device__ __forceinline__ void fma2(ull& d, ull a, ull b) {
    asm("fma.rn.f32x2 %0, %1, %2, %0;" : "+l"(d) : "l"(a), "l"(b));
}
__device__ __forceinline__ ull add2(ull a, ull b) {
    ull r; asm("add.rn.f32x2 %0, %1, %2;" : "=l"(r) : "l"(a), "l"(b)); return r;
}
__device__ __forceinline__ ull pack2(float v) {
    ull r; asm("mov.b64 %0, {%1, %1};" : "=l"(r) : "r"(__float_as_uint(v))); return r;
}
__device__ __forceinline__ ull pk(float a, float b) {
    ull r; asm("mov.b64 %0, {%1, %2};" : "=l"(r) : "r"(__float_as_uint(a)), "r"(__float_as_uint(b))); return r;
}
__device__ __forceinline__ float2 unpk(ull a) {
    float2 f; asm("mov.b64 {%0, %1}, %2;" : "=f"(f.x), "=f"(f.y) : "l"(a)); return f;
}
__device__ __forceinline__ float sum2(ull a) { float2 f = unpk(a); return f.x + f.y; }

__device__ __forceinline__ void mbar_init(unsigned mbar, unsigned cnt) {
    asm volatile("mbarrier.init.shared.b64 [%0], %1;" :: "r"(mbar), "r"(cnt) : "memory");
}
__device__ __forceinline__ void mbar_expect(unsigned mbar, unsigned bytes) {
    asm volatile("mbarrier.arrive.expect_tx.shared.b64 _, [%0], %1;" :: "r"(mbar), "r"(bytes) : "memory");
}
__device__ __forceinline__ void bulk_g2s(unsigned dst, const void* src, unsigned mbar) {
    asm volatile("cp.async.bulk.shared::cluster.global.mbarrier::complete_tx::bytes [%0], [%1], 512, [%2];"
                 :: "r"(dst), "l"(src), "r"(mbar) : "memory");
}
__device__ __forceinline__ void bulk_g2s_sz(unsigned dst, const void* src, unsigned sz, unsigned mbar) {
    asm volatile("cp.async.bulk.shared::cluster.global.mbarrier::complete_tx::bytes [%0], [%1], %2, [%3];"
                 :: "r"(dst), "l"(src), "r"(sz), "r"(mbar) : "memory");
}
__device__ __forceinline__ void mbar_wait(unsigned mbar, unsigned parity) {
    unsigned done;
    asm volatile("{\n\t.reg .pred p;\n\t"
                 "mbarrier.try_wait.parity.acquire.cta.shared::cta.b64 p, [%1], %2;\n\t"
                 "selp.b32 %0, 1, 0, p;\n\t}"
                 : "=r"(done) : "r"(mbar), "r"(parity) : "memory");
    while (!done) {
        asm volatile("{\n\t.reg .pred p;\n\t"
                     "mbarrier.try_wait.parity.acquire.cta.shared::cta.b64 p, [%1], %2, 0x989680;\n\t"
                     "selp.b32 %0, 1, 0, p;\n\t}"
                     : "=r"(done) : "r"(mbar), "r"(parity) : "memory");
    }
}

__device__ __forceinline__ void prefetchXbulk(unsigned xbase, long long b,
                                              const int* lst, int m,
                                              const float* nnode, const float* edge,
                                              const float* ntime, unsigned mbar, int t) {
    if (t == 0) mbar_expect(mbar, (unsigned)(m * 1536));
    if (t < 96) {
        int sp = t / 3, part = t - sp * 3;
        if (sp < m) {
            long long row = (b * 32 + lst[sp]) * 128;
            const float* src = (part == 0) ? nnode + row : (part == 1) ? edge + row : ntime + row;
            unsigned dst = xbase + (unsigned)(sp * XSTR + part * 128) * 4u;
            bulk_g2s(dst, src, mbar);
        }
    }
}

__global__ __launch_bounds__(NT, 1)
void ta_kernel(const float* __restrict__ node, const float* __restrict__ timef,
               const float* __restrict__ edge, const float* __restrict__ nnode,
               const float* __restrict__ ntime, const int* __restrict__ mask,
               const float* __restrict__ WQ, const float* __restrict__ WKV,
               const float* __restrict__ WO, const float* __restrict__ bO,
               const float* __restrict__ gamma, const float* __restrict__ beta,
               float* __restrict__ out, int B)
{
    extern __shared__ float smf[];
    float* RT  = smf + RT_OFF;
    float* Qs  = smf + QS_OFF;
    float* PY  = smf + PY_OFF;
    float* XS  = smf + XS_OFF;
    float* XS1 = smf + XS1_OFF;
    float* woS = smf + WO_OFF;
    float* Wt  = smf + WT_OFF;
    float* red1 = smf + RD1_OFF;
    float* red2 = smf + RD2_OFF;
    float* muS = smf + MU_OFF;
    float* rsS = smf + RS_OFF;
    int* codeS = (int*)(smf + CODE_OFF);
    int* lstS  = (int*)(smf + LST_OFF);
    int* mS    = (int*)(smf + MS_OFF);

    const int t = threadIdx.x;
    const int wid = t >> 5, lane = t & 31;
    const int b0 = blockIdx.x * G;

    const unsigned xsBase  = (unsigned)__cvta_generic_to_shared(XS);
    const unsigned mbX0    = (unsigned)__cvta_generic_to_shared(smf + MB_OFF);
    const unsigned mbX1    = mbX0 + 8;
    const unsigned mbWO    = mbX0 + 16;

    // phase 0a: mbarrier init + masks + compaction
    if (t == 0) {
        mbar_init(mbX0, 1);
        mbar_init(mbX1, 1);
        mbar_init(mbWO, 1);
    }
    if (t < 256) {
        int g = wid;
        int bb = b0 + g; if (bb > B - 1) bb = B - 1;
        int mk = mask[(long long)bb * 32 + lane];
        unsigned bal = __ballot_sync(0xffffffffu, mk != 0);
        int m = __popc(bal);
        if (m == 0) {
            codeS[g * 32 + lane] = 2;
            lstS[g * 32 + lane] = lane;
            if (lane == 0) mS[g] = 32;
        } else {
            codeS[g * 32 + lane] = mk ? 0 : 1;
            if (mk) lstS[g * 32 + __popc(bal & ((1u << lane) - 1u))] = lane;
            if (lane == 0) mS[g] = m;
        }
    }
    __syncthreads();

    // bulk prefetch X[0] into buffer 0
    {
        int bb = b0; if (bb > B - 1) bb = B - 1;
        prefetchXbulk(xsBase, (long long)bb, &lstS[0], mS[0], nnode, edge, ntime, mbX0, t);
    }

    // phase 0b: RT
    for (int idx = t; idx < G * 256; idx += NT) {
        int g = idx & 7, j = idx >> 3;
        int bb = b0 + g; if (bb > B - 1) bb = B - 1;
        long long b = bb;
        RT[j * G + g] = (j < 128) ? node[b * 128 + j] : timef[b * 128 + (j - 128)];
    }
    __syncthreads();

    // phase 1: Q partials (staged in XS1)
    {
        const int o = t & 255, q = t >> 8;
        ull a0 = 0, a1 = 0, a2 = 0, a3 = 0;
        const int i0 = q * 64;
        const ull* RT2 = (const ull*)RT;
#pragma unroll 4
        for (int ii = 0; ii < 64; ++ii) {
            int i = i0 + ii;
            ull w2 = pack2(__ldg(&WQ[i * 256 + o]));
            ulonglong2 ra = *(const ulonglong2*)&RT2[i * 4];
            ulonglong2 rb = *(const ulonglong2*)&RT2[i * 4 + 2];
            fma2(a0, ra.x, w2); fma2(a1, ra.y, w2);
            fma2(a2, rb.x, w2); fma2(a3, rb.y, w2);
        }
        ull* stg = (ull*)(XS1 + q * 2048 + o * 8);
        ((ulonglong2*)stg)[0] = make_ulonglong2(a0, a1);
        ((ulonglong2*)stg)[1] = make_ulonglong2(a2, a3);
    }
    __syncthreads();
    {
        const ull* S = (const ull*)XS1;
        ((ull*)Qs)[t] = add2(add2(S[t], S[1024 + t]), add2(S[2048 + t], S[3072 + t]));
    }
    __syncthreads();

    // phase 2: P[g][h][i], coalesced WKV
    {
        const int h = wid >> 2, ic = wid & 3;
        const int il = lane >> 3, q = lane & 7;
        const int q1 = q & 1, q2 = (q >> 1) & 1, q4 = (q >> 2) & 1;
        ull Qp[4][4];
        const ull* Q2 = (const ull*)Qs;
#pragma unroll
        for (int e = 0; e < 4; ++e) {
            int c = h * 32 + q * 4 + e;
            ulonglong2 qa = *(const ulonglong2*)&Q2[c * 4];
            ulonglong2 qb = *(const ulonglong2*)&Q2[c * 4 + 2];
            Qp[e][0] = qa.x; Qp[e][1] = qa.y; Qp[e][2] = qb.x; Qp[e][3] = qb.y;
        }
        const int ibase = ic * 96 + il;
#pragma unroll 2
        for (int it = 0; it < 24; ++it) {
            int i = ibase + it * 4;
            float4 wv = __ldg((const float4*)&WKV[(size_t)i * 512 + h * 32 + q * 4]);
            ull acc[4] = {0, 0, 0, 0};
#pragma unroll
            for (int e = 0; e < 4; ++e) {
                ull wp = pack2((&wv.x)[e]);
                fma2(acc[0], Qp[e][0], wp); fma2(acc[1], Qp[e][1], wp);
                fma2(acc[2], Qp[e][2], wp); fma2(acc[3], Qp[e][3], wp);
            }
            float v[8];
#pragma unroll
            for (int p = 0; p < 4; ++p) { float2 f = unpk(acc[p]); v[2*p] = f.x; v[2*p+1] = f.y; }
            float u[4];
#pragma unroll
            for (int j = 0; j < 4; ++j) {
                float a = v[2*j], b = v[2*j+1];
                float mine = q1 ? b : a, send = q1 ? a : b;
                u[j] = mine + __shfl_xor_sync(0xffffffffu, send, 1);
            }
            float w2_[2];
#pragma unroll
            for (int kk = 0; kk < 2; ++kk) {
                float a = u[2*kk], b = u[2*kk+1];
                float mine = q2 ? b : a, send = q2 ? a : b;
                w2_[kk] = mine + __shfl_xor_sync(0xffffffffu, send, 2);
            }
            float a = w2_[0], b = w2_[1];
            float mine = q4 ? b : a, send = q4 ? a : b;
            PY[(q * 8 + h) * PSTR + i] = mine + __shfl_xor_sync(0xffffffffu, send, 4);
        }
    }
    mbar_wait(mbX0, 0);
    __syncthreads();

    // phase 3: per-g attention
    float* AttP = Qs;    // [8 slot][32 s][8 h] = 2048 floats
#pragma unroll 1
    for (int g = 0; g < G; ++g) {
        float* Xbuf = XS + (g & 1) * 12416;
        const int m = mS[g];

        if (g < G - 1) {
            int bb = b0 + g + 1; if (bb > B - 1) bb = B - 1;
            prefetchXbulk(xsBase + ((unsigned)((g + 1) & 1)) * (12416u * 4u), (long long)bb,
                          &lstS[(g + 1) * 32], mS[g + 1], nnode, edge, ntime,
                          ((g + 1) & 1) ? mbX1 : mbX0, t);
        }

        // scores 2x2 register-blocked: warp = (sq 0..3 covering 8 s, iqil 0..7 of 48-fl chunks)
        // lane = (sp2 = lane>>3, hp = (lane>>1)&3, jh = lane&1 splitting chunk in 24-fl halves)
        {
            const int sq = wid >> 3, iqil = wid & 7;
            const int sp2 = lane >> 3, hp = (lane >> 1) & 3, jh = lane & 1;
            if (sq * 8 < m) {
                const int s0 = sq * 8 + sp2 * 2, s1 = s0 + 1;
                const bool v0 = s0 < m, v1 = s1 < m;
                const int s0c = v0 ? s0 : m - 1, s1c = v1 ? s1 : m - 1;
                const int off = iqil * 48 + jh * 24;
                const ulonglong2* Xa = (const ulonglong2*)&Xbuf[s0c * XSTR + off];
                const ulonglong2* Xb = (const ulonglong2*)&Xbuf[s1c * XSTR + off];
                const ulonglong2* Pa = (const ulonglong2*)&PY[(g * 8 + hp * 2) * PSTR + off];
                const ulonglong2* Pb = (const ulonglong2*)&PY[(g * 8 + hp * 2 + 1) * PSTR + off];
                ull a00 = 0, a01 = 0, a10 = 0, a11 = 0;
#pragma unroll
                for (int j = 0; j < 6; ++j) {
                    ulonglong2 xa = Xa[j], pa = Pa[j];
                    ulonglong2 xb = Xb[j], pb = Pb[j];
                    fma2(a00, xa.x, pa.x); fma2(a00, xa.y, pa.y);
                    fma2(a01, xa.x, pb.x); fma2(a01, xa.y, pb.y);
                    fma2(a10, xb.x, pa.x); fma2(a10, xb.y, pa.y);
                    fma2(a11, xb.x, pb.x); fma2(a11, xb.y, pb.y);
                }
                float f00 = sum2(a00), f01 = sum2(a01);
                float f10 = sum2(a10), f11 = sum2(a11);
                f00 += __shfl_xor_sync(0xffffffffu, f00, 1);
                f01 += __shfl_xor_sync(0xffffffffu, f01, 1);
                f10 += __shfl_xor_sync(0xffffffffu, f10, 1);
                f11 += __shfl_xor_sync(0xffffffffu, f11, 1);
                if (jh == 0) {
                    if (v0) *(float2*)&AttP[iqil * 256 + lstS[g * 32 + s0] * 8 + hp * 2]
                            = make_float2(f00, f01);
                    if (v1) *(float2*)&AttP[iqil * 256 + lstS[g * 32 + s1] * 8 + hp * 2]
                            = make_float2(f10, f11);
                }
            }
        }
        __syncthreads();

        // softmax: warp h (wid<8), lane = s; 8 chunk partials
        if (wid < 8) {
            const int s = lane;
            int cde = codeS[g * 32 + s];
            float a = 0.f;
#pragma unroll
            for (int sl8 = 0; sl8 < 8; ++sl8)
                a += AttP[sl8 * 256 + s * 8 + wid];
            float v = (cde == 0) ? a * 0.17677669529663687f
                                 : ((cde == 1) ? -1e10f : 0.f);
            float mx = wmax(v);
            float e = __expf(v - mx);
            float ss = wsum(e);
            Wt[s * 8 + wid] = e / ss;     // [s][8h]
        }
        __syncthreads();

        // Y[g][*][col]: 384 threads, broadcast head-pair weights
        if (t < 384) {
            const int col = t;
            ull acc0 = 0, acc1 = 0, acc2 = 0, acc3 = 0;
#pragma unroll 2
            for (int sp = 0; sp < m; ++sp) {
                int so = lstS[g * 32 + sp];
                ull x2 = pack2(Xbuf[sp * XSTR + col]);
                ulonglong2 wa = *(const ulonglong2*)&Wt[so * 8];
                ulonglong2 wb = *(const ulonglong2*)&Wt[so * 8 + 4];
                fma2(acc0, x2, wa.x); fma2(acc1, x2, wa.y);
                fma2(acc2, x2, wb.x); fma2(acc3, x2, wb.y);
            }
            float2 y01 = unpk(acc0), y23 = unpk(acc1);
            float2 y45 = unpk(acc2), y67 = unpk(acc3);
            PY[(g * 8 + 0) * PSTR + col] = y01.x;
            PY[(g * 8 + 1) * PSTR + col] = y01.y;
            PY[(g * 8 + 2) * PSTR + col] = y23.x;
            PY[(g * 8 + 3) * PSTR + col] = y23.y;
            PY[(g * 8 + 4) * PSTR + col] = y45.x;
            PY[(g * 8 + 5) * PSTR + col] = y45.y;
            PY[(g * 8 + 6) * PSTR + col] = y67.x;
            PY[(g * 8 + 7) * PSTR + col] = y67.y;
        }
        if (g < G - 1)
            mbar_wait(((g + 1) & 1) ? mbX1 : mbX0, ((g + 1) >> 1) & 1);
        __syncthreads();
    }

    // stage WO rows i=0..63 via bulk DMA (overlaps phase 4)
    if (t < 4) {
        if (t == 0) mbar_expect(mbWO, 65536u);
        unsigned dst = (unsigned)__cvta_generic_to_shared(woS) + (unsigned)t * 16384u;
        bulk_g2s_sz(dst, WO + t * 4096, 16384u, mbWO);
    }

    // phase 4: O partials (staged in XS[0..8191])
    {
        const int o = t & 255, q = t >> 8, h = o >> 5;
        ull acc2[8];
#pragma unroll
        for (int g = 0; g < 8; ++g) acc2[g] = 0;
        const float* wvp = WKV + 256 + o;
        const int i0 = q * 96;
#pragma unroll 2
        for (int j = 0; j < 24; ++j) {
            int i = i0 + j * 4;
            float w0 = __ldg(&wvp[(size_t)(i + 0) * 512]);
            float w1 = __ldg(&wvp[(size_t)(i + 1) * 512]);
            float w2 = __ldg(&wvp[(size_t)(i + 2) * 512]);
            float w3 = __ldg(&wvp[(size_t)(i + 3) * 512]);
            ull wp01 = pk(w0, w1), wp23 = pk(w2, w3);
#pragma unroll
            for (int g = 0; g < 8; ++g) {
                ulonglong2 y = *(const ulonglong2*)&PY[(g * 8 + h) * PSTR + i];
                fma2(acc2[g], y.x, wp01);
                fma2(acc2[g], y.y, wp23);
            }
        }
        float r[8];
#pragma unroll
        for (int g = 0; g < 8; ++g) r[g] = sum2(acc2[g]);
        float* stg = XS + q * 2048 + o * 8;
        *(float4*)stg       = make_float4(r[0], r[1], r[2], r[3]);
        *(float4*)(stg + 4) = make_float4(r[4], r[5], r[6], r[7]);
    }
    mbar_wait(mbWO, 0);
    __syncthreads();
    {
        const ull* S = (const ull*)XS;
        ((ull*)Qs)[t] = add2(add2(S[t], S[1024 + t]), add2(S[2048 + t], S[3072 + t]));
    }
    __syncthreads();

    // phase 5: out-proj partials; q==0 reads WO from smem
    {
        const int o = t & 255, q = t >> 8;
        ull a0 = 0, a1 = 0, a2 = 0, a3 = 0;
        const ull* O2 = (const ull*)Qs;
        if (q == 0) {
#pragma unroll 4
            for (int i = 0; i < 64; ++i) {
                ull wp = pack2(woS[i * 256 + o]);
                ulonglong2 va = *(const ulonglong2*)&O2[i * 4];
                ulonglong2 vb = *(const ulonglong2*)&O2[i * 4 + 2];
                fma2(a0, va.x, wp); fma2(a1, va.y, wp);
                fma2(a2, vb.x, wp); fma2(a3, vb.y, wp);
            }
        } else {
            const int i0 = q * 64;
#pragma unroll 4
            for (int ii = 0; ii < 64; ++ii) {
                int i = i0 + ii;
                ull wp = pack2(__ldg(&WO[i * 256 + o]));
                ulonglong2 va = *(const ulonglong2*)&O2[i * 4];
                ulonglong2 vb = *(const ulonglong2*)&O2[i * 4 + 2];
                fma2(a0, va.x, wp); fma2(a1, va.y, wp);
                fma2(a2, vb.x, wp); fma2(a3, vb.y, wp);
            }
        }
        __syncthreads();
        float2 f0 = unpk(a0), f1 = unpk(a1), f2 = unpk(a2), f3 = unpk(a3);
        float* stg = XS + q * 2048 + o * 8;
        *(float4*)stg       = make_float4(f0.x, f0.y, f1.x, f1.y);
        *(float4*)(stg + 4) = make_float4(f2.x, f2.y, f3.x, f3.y);
    }
    __syncthreads();

    // residual + LayerNorm
    {
        const int o = t & 255, gp = t >> 8;
        float xg[2];
#pragma unroll
        for (int j = 0; j < 2; ++j) {
            int g = gp * 2 + j;
            int idx = o * 8 + g;
            float s = XS[idx] + XS[2048 + idx] + XS[4096 + idx] + XS[6144 + idx];
            xg[j] = s + __ldg(&bO[o]) + RT[o * 8 + g];
            float s1 = wsum(xg[j]);
            float s2 = wsum(xg[j] * xg[j]);
            if (lane == 0) { red1[wid * 2 + j] = s1; red2[wid * 2 + j] = s2; }
        }
        __syncthreads();
        if (t < 8) {
            int g = t, gq = g >> 1, j = g & 1;
            float t1 = 0.f, t2 = 0.f;
#pragma unroll
            for (int w = 0; w < 8; ++w) {
                t1 += red1[(gq * 8 + w) * 2 + j];
                t2 += red2[(gq * 8 + w) * 2 + j];
            }
            float mu = t1 * (1.0f / 256.0f);
            float var = t2 * (1.0f / 256.0f) - mu * mu;
            muS[g] = mu;
            rsS[g] = rsqrtf(var + 1e-5f);
        }
        __syncthreads();
        float gm = __ldg(&gamma[o]), bt = __ldg(&beta[o]);
#pragma unroll
        for (int j = 0; j < 2; ++j) {
            int g = gp * 2 + j;
            int b = b0 + g;
            if (b < B)
                out[(size_t)b * 256 + o] = (xg[j] - muS[g]) * rsS[g] * gm + bt;
        }
    }
}

extern "C" void kernel_launch(void* const* d_in, const int* in_sizes, int n_in,
                              void* d_out, int out_size) {
    (void)n_in; (void)out_size;
    const float* node  = (const float*)d_in[0];
    const float* timef = (const float*)d_in[1];
    const float* edge  = (const float*)d_in[2];
    const float* nnode = (const float*)d_in[3];
    const float* ntime = (const float*)d_in[4];
    const int*   mask  = (const int*)d_in[5];
    const float* WQ    = (const float*)d_in[6];
    const float* WKV   = (const float*)d_in[7];
    const float* WO    = (const float*)d_in[8];
    const float* bO    = (const float*)d_in[9];
    const float* gamma = (const float*)d_in[10];
    const float* beta  = (const float*)d_in[11];
    float* out = (float*)d_out;

    int B = in_sizes[0] / 128;
    int blocks = (B + G - 1) / G;

    cudaFuncSetAttribute(ta_kernel, cudaFuncAttributeMaxDynamicSharedMemorySize, SMEM_BYTES);
    ta_kernel<<<blocks, NT, SMEM_BYTES>>>(node, timef, edge, nnode, ntime, mask,
                                          WQ, WKV, WO, bO, gamma, beta, out, B);
}

// round 15
// speedup vs baseline: 1.0465x; 1.0465x over previous
#include <cuda_runtime.h>
#include <math.h>

typedef unsigned long long ull;

#define G    8
#define NT   1024
#define XSTR 388
#define PSTR 388
#define GSTR 3108                          // 8*PSTR + 4  (== 4 mod 32)

#define RT_OFF   0
#define QS_OFF   2048
#define PY_OFF   4096
#define XS_OFF   (PY_OFF + 24864)          // 8*GSTR = 24864
#define XS1_OFF  (XS_OFF + 12416)
#define WO_OFF   (XS_OFF + 8192)
#define WT_OFF   (XS_OFF + 24832)
#define RD1_OFF  (WT_OFF + 256)
#define RD2_OFF  (RD1_OFF + 64)
#define MU_OFF   (RD2_OFF + 64)
#define RS_OFF   (MU_OFF + 8)
#define CODE_OFF (RS_OFF + 8)
#define LST_OFF  (CODE_OFF + 256)
#define MS_OFF   (LST_OFF + 256)
#define MB_OFF   (MS_OFF + 8)
#define SMEM_FLOATS (MB_OFF + 8)
#define SMEM_BYTES  (SMEM_FLOATS * 4)

__device__ __forceinline__ float wsum(float v) {
#pragma unroll
    for (int o = 16; o > 0; o >>= 1) v += __shfl_xor_sync(0xffffffffu, v, o);
    return v;
}
__device__ __forceinline__ float wmax(float v) {
#pragma unroll
    for (int o = 16; o > 0; o >>= 1) v = fmaxf(v, __shfl_xor_sync(0xffffffffu, v, o));
    return v;
}
__device__ __forceinline__ void fma2(ull& d, ull a, ull b) {
    asm("fma.rn.f32x2 %0, %1, %2, %0;" : "+l"(d) : "l"(a), "l"(b));
}
__device__ __forceinline__ ull add2(ull a, ull b) {
    ull r; asm("add.rn.f32x2 %0, %1, %2;" : "=l"(r) : "l"(a), "l"(b)); return r;
}
__device__ __forceinline__ ull pack2(float v) {
    ull r; asm("mov.b64 %0, {%1, %1};" : "=l"(r) : "r"(__float_as_uint(v))); return r;
}
__device__ __forceinline__ ull pk(float a, float b) {
    ull r; asm("mov.b64 %0, {%1, %2};" : "=l"(r) : "r"(__float_as_uint(a)), "r"(__float_as_uint(b))); return r;
}
__device__ __forceinline__ float2 unpk(ull a) {
    float2 f; asm("mov.b64 {%0, %1}, %2;" : "=f"(f.x), "=f"(f.y) : "l"(a)); return f;
}
__device__ __forceinline__ float sum2(ull a) { float2 f = unpk(a); return f.x + f.y; }

__device__ __forceinline__ void mbar_init(unsigned mbar, unsigned cnt) {
    asm volatile("mbarrier.init.shared.b64 [%0], %1;" :: "r"(mbar), "r"(cnt) : "memory");
}
__device__ __forceinline__ void mbar_expect(unsigned mbar, unsigned bytes) {
    asm volatile("mbarrier.arrive.expect_tx.shared.b64 _, [%0], %1;" :: "r"(mbar), "r"(bytes) : "memory");
}
__device__ __forceinline__ void bulk_g2s(unsigned dst, const void* src, unsigned mbar) {
    asm volatile("cp.async.bulk.shared::cluster.global.mbarrier::complete_tx::bytes [%0], [%1], 512, [%2];"
                 :: "r"(dst), "l"(src), "r"(mbar) : "memory");
}
__device__ __forceinline__ void bulk_g2s_sz(unsigned dst, const void* src, unsigned sz, unsigned mbar) {
    asm volatile("cp.async.bulk.shared::cluster.global.mbarrier::complete_tx::bytes [%0], [%1], %2, [%3];"
                 :: "r"(dst), "l"(src), "r"(sz), "r"(mbar) : "memory");
}
__device__ __forceinline__ void mbar_wait(unsigned mbar, unsigned parity) {
    unsigned done;
    asm volatile("{\n\t.reg .pred p;\n\t"
                 "mbarrier.try_wait.parity.acquire.cta.shared::cta.b64 p, [%1], %2;\n\t"
                 "selp.b32 %0, 1, 0, p;\n\t}"
                 : "=r"(done) : "r"(mbar), "r"(parity) : "memory");
    while (!done) {
        asm volatile("{\n\t.reg .pred p;\n\t"
                     "mbarrier.try_wait.parity.acquire.cta.shared::cta.b64 p, [%1], %2, 0x989680;\n\t"
                     "selp.b32 %0, 1, 0, p;\n\t}"
                     : "=r"(done) : "r"(mbar), "r"(parity) : "memory");
    }
}

__device__ __forceinline__ void prefetchXbulk(unsigned xbase, long long b,
                                              const int* lst, int m,
                                              const float* nnode, const float* edge,
                                              const float* ntime, unsigned mbar, int t) {
    if (t == 0) mbar_expect(mbar, (unsigned)(m * 1536));
    if (t < 96) {
        int sp = t / 3, part = t - sp * 3;
        if (sp < m) {
            long long row = (b * 32 + lst[sp]) * 128;
            const float* src = (part == 0) ? nnode + row : (part == 1) ? edge + row : ntime + row;
            unsigned dst = xbase + (unsigned)(sp * XSTR + part * 128) * 4u;
            bulk_g2s(dst, src, mbar);
        }
    }
}

__global__ __launch_bounds__(NT, 1)
void ta_kernel(const float* __restrict__ node, const float* __restrict__ timef,
               const float* __restrict__ edge, const float* __restrict__ nnode,
               const float* __restrict__ ntime, const int* __restrict__ mask,
               const float* __restrict__ WQ, const float* __restrict__ WKV,
               const float* __restrict__ WO, const float* __restrict__ bO,
               const float* __restrict__ gamma, const float* __restrict__ beta,
               float* __restrict__ out, int B)
{
    extern __shared__ float smf[];
    float* RT  = smf + RT_OFF;
    float* Qs  = smf + QS_OFF;
    float* PY  = smf + PY_OFF;
    float* XS  = smf + XS_OFF;
    float* XS1 = smf + XS1_OFF;
    float* woS = smf + WO_OFF;
    float* Wt  = smf + WT_OFF;
    float* red1 = smf + RD1_OFF;
    float* red2 = smf + RD2_OFF;
    float* muS = smf + MU_OFF;
    float* rsS = smf + RS_OFF;
    int* codeS = (int*)(smf + CODE_OFF);
    int* lstS  = (int*)(smf + LST_OFF);
    int* mS    = (int*)(smf + MS_OFF);

    const int t = threadIdx.x;
    const int wid = t >> 5, lane = t & 31;
    const int b0 = blockIdx.x * G;

    const unsigned xsBase  = (unsigned)__cvta_generic_to_shared(XS);
    const unsigned mbX0    = (unsigned)__cvta_generic_to_shared(smf + MB_OFF);
    const unsigned mbX1    = mbX0 + 8;
    const unsigned mbWO    = mbX0 + 16;

    // phase 0a: mbarrier init + masks + compaction
    if (t == 0) {
        mbar_init(mbX0, 1);
        mbar_init(mbX1, 1);
        mbar_init(mbWO, 1);
    }
    if (t < 256) {
        int g = wid;
        int bb = b0 + g; if (bb > B - 1) bb = B - 1;
        int mk = mask[(long long)bb * 32 + lane];
        unsigned bal = __ballot_sync(0xffffffffu, mk != 0);
        int m = __popc(bal);
        if (m == 0) {
            codeS[g * 32 + lane] = 2;
            lstS[g * 32 + lane] = lane;
            if (lane == 0) mS[g] = 32;
        } else {
            codeS[g * 32 + lane] = mk ? 0 : 1;
            if (mk) lstS[g * 32 + __popc(bal & ((1u << lane) - 1u))] = lane;
            if (lane == 0) mS[g] = m;
        }
    }
    __syncthreads();

    // bulk prefetch X[0] into buffer 0
    {
        int bb = b0; if (bb > B - 1) bb = B - 1;
        prefetchXbulk(xsBase, (long long)bb, &lstS[0], mS[0], nnode, edge, ntime, mbX0, t);
    }

    // phase 0b: RT
    for (int idx = t; idx < G * 256; idx += NT) {
        int g = idx & 7, j = idx >> 3;
        int bb = b0 + g; if (bb > B - 1) bb = B - 1;
        long long b = bb;
        RT[j * G + g] = (j < 128) ? node[b * 128 + j] : timef[b * 128 + (j - 128)];
    }
    __syncthreads();

    // phase 1: Q partials (staged in XS1)
    {
        const int o = t & 255, q = t >> 8;
        ull a0 = 0, a1 = 0, a2 = 0, a3 = 0;
        const int i0 = q * 64;
        const ull* RT2 = (const ull*)RT;
#pragma unroll 4
        for (int ii = 0; ii < 64; ++ii) {
            int i = i0 + ii;
            ull w2 = pack2(__ldg(&WQ[i * 256 + o]));
            ulonglong2 ra = *(const ulonglong2*)&RT2[i * 4];
            ulonglong2 rb = *(const ulonglong2*)&RT2[i * 4 + 2];
            fma2(a0, ra.x, w2); fma2(a1, ra.y, w2);
            fma2(a2, rb.x, w2); fma2(a3, rb.y, w2);
        }
        ull* stg = (ull*)(XS1 + q * 2048 + o * 8);
        ((ulonglong2*)stg)[0] = make_ulonglong2(a0, a1);
        ((ulonglong2*)stg)[1] = make_ulonglong2(a2, a3);
    }
    __syncthreads();
    {
        const ull* S = (const ull*)XS1;
        ((ull*)Qs)[t] = add2(add2(S[t], S[1024 + t]), add2(S[2048 + t], S[3072 + t]));
    }
    __syncthreads();

    // phase 2: P[g][h][i], coalesced WKV; conflict-free stores via GSTR
    {
        const int h = wid >> 2, ic = wid & 3;
        const int il = lane >> 3, q = lane & 7;
        const int q1 = q & 1, q2 = (q >> 1) & 1, q4 = (q >> 2) & 1;
        ull Qp[4][4];
        const ull* Q2 = (const ull*)Qs;
#pragma unroll
        for (int e = 0; e < 4; ++e) {
            int c = h * 32 + q * 4 + e;
            ulonglong2 qa = *(const ulonglong2*)&Q2[c * 4];
            ulonglong2 qb = *(const ulonglong2*)&Q2[c * 4 + 2];
            Qp[e][0] = qa.x; Qp[e][1] = qa.y; Qp[e][2] = qb.x; Qp[e][3] = qb.y;
        }
        const int ibase = ic * 96 + il;
#pragma unroll 2
        for (int it = 0; it < 24; ++it) {
            int i = ibase + it * 4;
            float4 wv = __ldg((const float4*)&WKV[(size_t)i * 512 + h * 32 + q * 4]);
            ull acc[4] = {0, 0, 0, 0};
#pragma unroll
            for (int e = 0; e < 4; ++e) {
                ull wp = pack2((&wv.x)[e]);
                fma2(acc[0], Qp[e][0], wp); fma2(acc[1], Qp[e][1], wp);
                fma2(acc[2], Qp[e][2], wp); fma2(acc[3], Qp[e][3], wp);
            }
            float v[8];
#pragma unroll
            for (int p = 0; p < 4; ++p) { float2 f = unpk(acc[p]); v[2*p] = f.x; v[2*p+1] = f.y; }
            float u[4];
#pragma unroll
            for (int j = 0; j < 4; ++j) {
                float a = v[2*j], b = v[2*j+1];
                float mine = q1 ? b : a, send = q1 ? a : b;
                u[j] = mine + __shfl_xor_sync(0xffffffffu, send, 1);
            }
            float w2_[2];
#pragma unroll
            for (int kk = 0; kk < 2; ++kk) {
                float a = u[2*kk], b = u[2*kk+1];
                float mine = q2 ? b : a, send = q2 ? a : b;
                w2_[kk] = mine + __shfl_xor_sync(0xffffffffu, send, 2);
            }
            float a = w2_[0], b = w2_[1];
            float mine = q4 ? b : a, send = q4 ? a : b;
            PY[q * GSTR + h * PSTR + i] = mine + __shfl_xor_sync(0xffffffffu, send, 4);
        }
    }
    mbar_wait(mbX0, 0);
    __syncthreads();

    // phase 3: per-g attention (R13 schedule, 4-way score split)
    float* AttP = Qs;
#pragma unroll 1
    for (int g = 0; g < G; ++g) {
        float* Xbuf = XS + (g & 1) * 12416;
        const int m = mS[g];

        if (g < G - 1) {
            int bb = b0 + g + 1; if (bb > B - 1) bb = B - 1;
            prefetchXbulk(xsBase + ((unsigned)((g + 1) & 1)) * (12416u * 4u), (long long)bb,
                          &lstS[(g + 1) * 32], mS[g + 1], nnode, edge, ntime,
                          ((g + 1) & 1) ? mbX1 : mbX0, t);
        }

        // scores: warp = (sq 0..7, iq 0..3); lane = (h, sl)
        {
            const int sq = wid >> 2, iq = wid & 3;
            const int h = lane >> 2, sl = lane & 3;
            if (sq * 4 < m) {
                int sp = sq * 4 + sl;
                bool valid = sp < m;
                int spc = valid ? sp : (m - 1);
                const ulonglong2* X2 = (const ulonglong2*)&Xbuf[spc * XSTR + iq * 96];
                const ulonglong2* P2 = (const ulonglong2*)&PY[g * GSTR + h * PSTR + iq * 96];
                ull a0 = 0, a1 = 0;
#pragma unroll
                for (int j = 0; j < 24; j += 2) {
                    ulonglong2 x0 = X2[j], p0 = P2[j];
                    ulonglong2 x1 = X2[j + 1], p1 = P2[j + 1];
                    fma2(a0, x0.x, p0.x); fma2(a0, x0.y, p0.y);
                    fma2(a1, x1.x, p1.x); fma2(a1, x1.y, p1.y);
                }
                if (valid)
                    AttP[iq * 256 + lstS[g * 32 + sp] * 8 + h] = sum2(add2(a0, a1));
            }
        }
        __syncthreads();

        // softmax
        if (wid < 8) {
            const int s = lane;
            int cde = codeS[g * 32 + s];
            float a = AttP[s * 8 + wid] + AttP[256 + s * 8 + wid]
                    + AttP[512 + s * 8 + wid] + AttP[768 + s * 8 + wid];
            float v = (cde == 0) ? a * 0.17677669529663687f
                                 : ((cde == 1) ? -1e10f : 0.f);
            float mx = wmax(v);
            float e = __expf(v - mx);
            float ss = wsum(e);
            Wt[s * 8 + wid] = e / ss;     // [s][8h]
        }
        __syncthreads();

        // Y[g][*][col]: 384 threads, broadcast head-pair weights
        if (t < 384) {
            const int col = t;
            ull acc0 = 0, acc1 = 0, acc2 = 0, acc3 = 0;
#pragma unroll 2
            for (int sp = 0; sp < m; ++sp) {
                int so = lstS[g * 32 + sp];
                ull x2 = pack2(Xbuf[sp * XSTR + col]);
                ulonglong2 wa = *(const ulonglong2*)&Wt[so * 8];
                ulonglong2 wb = *(const ulonglong2*)&Wt[so * 8 + 4];
                fma2(acc0, x2, wa.x); fma2(acc1, x2, wa.y);
                fma2(acc2, x2, wb.x); fma2(acc3, x2, wb.y);
            }
            float2 y01 = unpk(acc0), y23 = unpk(acc1);
            float2 y45 = unpk(acc2), y67 = unpk(acc3);
            PY[g * GSTR + 0 * PSTR + col] = y01.x;
            PY[g * GSTR + 1 * PSTR + col] = y01.y;
            PY[g * GSTR + 2 * PSTR + col] = y23.x;
            PY[g * GSTR + 3 * PSTR + col] = y23.y;
            PY[g * GSTR + 4 * PSTR + col] = y45.x;
            PY[g * GSTR + 5 * PSTR + col] = y45.y;
            PY[g * GSTR + 6 * PSTR + col] = y67.x;
            PY[g * GSTR + 7 * PSTR + col] = y67.y;
        }
        if (g < G - 1)
            mbar_wait(((g + 1) & 1) ? mbX1 : mbX0, ((g + 1) >> 1) & 1);
        __syncthreads();
    }

    // stage WO rows i=0..63 via bulk DMA (overlaps phase 4)
    if (t < 4) {
        if (t == 0) mbar_expect(mbWO, 65536u);
        unsigned dst = (unsigned)__cvta_generic_to_shared(woS) + (unsigned)t * 16384u;
        bulk_g2s_sz(dst, WO + t * 4096, 16384u, mbWO);
    }

    // phase 4: O partials (staged in XS[0..8191])
    {
        const int o = t & 255, q = t >> 8, h = o >> 5;
        ull acc2[8];
#pragma unroll
        for (int g = 0; g < 8; ++g) acc2[g] = 0;
        const float* wvp = WKV + 256 + o;
        const int i0 = q * 96;
#pragma unroll 2
        for (int j = 0; j < 24; ++j) {
            int i = i0 + j * 4;
            float w0 = __ldg(&wvp[(size_t)(i + 0) * 512]);
            float w1 = __ldg(&wvp[(size_t)(i + 1) * 512]);
            float w2 = __ldg(&wvp[(size_t)(i + 2) * 512]);
            float w3 = __ldg(&wvp[(size_t)(i + 3) * 512]);
            ull wp01 = pk(w0, w1), wp23 = pk(w2, w3);
#pragma unroll
            for (int g = 0; g < 8; ++g) {
                ulonglong2 y = *(const ulonglong2*)&PY[g * GSTR + h * PSTR + i];
                fma2(acc2[g], y.x, wp01);
                fma2(acc2[g], y.y, wp23);
            }
        }
        float r[8];
#pragma unroll
        for (int g = 0; g < 8; ++g) r[g] = sum2(acc2[g]);
        float* stg = XS + q * 2048 + o * 8;
        *(float4*)stg       = make_float4(r[0], r[1], r[2], r[3]);
        *(float4*)(stg + 4) = make_float4(r[4], r[5], r[6], r[7]);
    }
    mbar_wait(mbWO, 0);
    __syncthreads();
    {
        const ull* S = (const ull*)XS;
        ((ull*)Qs)[t] = add2(add2(S[t], S[1024 + t]), add2(S[2048 + t], S[3072 + t]));
    }
    __syncthreads();

    // phase 5: out-proj partials; q==0 reads WO from smem
    {
        const int o = t & 255, q = t >> 8;
        ull a0 = 0, a1 = 0, a2 = 0, a3 = 0;
        const ull* O2 = (const ull*)Qs;
        if (q == 0) {
#pragma unroll 4
            for (int i = 0; i < 64; ++i) {
                ull wp = pack2(woS[i * 256 + o]);
                ulonglong2 va = *(const ulonglong2*)&O2[i * 4];
                ulonglong2 vb = *(const ulonglong2*)&O2[i * 4 + 2];
                fma2(a0, va.x, wp); fma2(a1, va.y, wp);
                fma2(a2, vb.x, wp); fma2(a3, vb.y, wp);
            }
        } else {
            const int i0 = q * 64;
#pragma unroll 4
            for (int ii = 0; ii < 64; ++ii) {
                int i = i0 + ii;
                ull wp = pack2(__ldg(&WO[i * 256 + o]));
                ulonglong2 va = *(const ulonglong2*)&O2[i * 4];
                ulonglong2 vb = *(const ulonglong2*)&O2[i * 4 + 2];
                fma2(a0, va.x, wp); fma2(a1, va.y, wp);
                fma2(a2, vb.x, wp); fma2(a3, vb.y, wp);
            }
        }
        __syncthreads();
        float2 f0 = unpk(a0), f1 = unpk(a1), f2 = unpk(a2), f3 = unpk(a3);
        float* stg = XS + q * 2048 + o * 8;
        *(float4*)stg       = make_float4(f0.x, f0.y, f1.x, f1.y);
        *(float4*)(stg + 4) = make_float4(f2.x, f2.y, f3.x, f3.y);
    }
    __syncthreads();

    // residual + LayerNorm
    {
        const int o = t & 255, gp = t >> 8;
        float xg[2];
#pragma unroll
        for (int j = 0; j < 2; ++j) {
            int g = gp * 2 + j;
            int idx = o * 8 + g;
            float s = XS[idx] + XS[2048 + idx] + XS[4096 + idx] + XS[6144 + idx];
            xg[j] = s + __ldg(&bO[o]) + RT[o * 8 + g];
            float s1 = wsum(xg[j]);
            float s2 = wsum(xg[j] * xg[j]);
            if (lane == 0) { red1[wid * 2 + j] = s1; red2[wid * 2 + j] = s2; }
        }
        __syncthreads();
        if (t < 8) {
            int g = t, gq = g >> 1, j = g & 1;
            float t1 = 0.f, t2 = 0.f;
#pragma unroll
            for (int w = 0; w < 8; ++w) {
                t1 += red1[(gq * 8 + w) * 2 + j];
                t2 += red2[(gq * 8 + w) * 2 + j];
            }
            float mu = t1 * (1.0f / 256.0f);
            float var = t2 * (1.0f / 256.0f) - mu * mu;
            muS[g] = mu;
            rsS[g] = rsqrtf(var + 1e-5f);
        }
        __syncthreads();
        float gm = __ldg(&gamma[o]), bt = __ldg(&beta[o]);
#pragma unroll
        for (int j = 0; j < 2; ++j) {
            int g = gp * 2 + j;
            int b = b0 + g;
            if (b < B)
                out[(size_t)b * 256 + o] = (xg[j] - muS[g]) * rsS[g] * gm + bt;
        }
    }
}

extern "C" void kernel_launch(void* const* d_in, const int* in_sizes, int n_in,
                              void* d_out, int out_size) {
    (void)n_in; (void)out_size;
    const float* node  = (const float*)d_in[0];
    const float* timef = (const float*)d_in[1];
    const float* edge  = (const float*)d_in[2];
    const float* nnode = (const float*)d_in[3];
    const float* ntime = (const float*)d_in[4];
    const int*   mask  = (const int*)d_in[5];
    const float* WQ    = (const float*)d_in[6];
    const float* WKV   = (const float*)d_in[7];
    const float* WO    = (const float*)d_in[8];
    const float* bO    = (const float*)d_in[9];
    const float* gamma = (const float*)d_in[10];
    const float* beta  = (const float*)d_in[11];
    float* out = (float*)d_out;

    int B = in_sizes[0] / 128;
    int blocks = (B + G - 1) / G;

    cudaFuncSetAttribute(ta_kernel, cudaFuncAttributeMaxDynamicSharedMemorySize, SMEM_BYTES);
    ta_kernel<<<blocks, NT, SMEM_BYTES>>>(node, timef, edge, nnode, ntime, mask,
                                          WQ, WKV, WO, bO, gamma, beta, out, B);
}